// round 15
// baseline (speedup 1.0000x reference)
#include <cuda_runtime.h>
#include <cuda_fp16.h>
#include <cstdint>

#define NROW 8192
#define FDIM 256
#define MT   64
#define KC   64
#define NCH  (NROW / KC)
#define NGRP (NROW / 128)

// ---------------- device globals (no runtime allocation) -------------------
__device__ __half g_hh[NROW * FDIM];     // h fp16 row-major (B operand)
__device__ float4 g_dE[NROW];            // (dst, e^dst, e^{0.2 dst}, src)
__device__ float  g_F [NROW];            // e^{-0.8 src}
__device__ uint4  g_abits[NROW * NGRP];  // adj bits: grp g, word u, bit l = adj[r][g*128+4l+u]

static __device__ __forceinline__ uint32_t smem_u32(const void* p) {
    return (uint32_t)__cvta_generic_to_shared(p);
}
static __device__ __forceinline__ void cp16(uint32_t dst, const void* src) {
    asm volatile("cp.async.cg.shared.global [%0], [%1], 16;\n" :: "r"(dst), "l"(src));
}
static __device__ __forceinline__ void cp_commit() {
    asm volatile("cp.async.commit_group;\n" ::: "memory");
}
static __device__ __forceinline__ void cp_wait_all() {
    asm volatile("cp.async.wait_group 0;\n" ::: "memory");
}

// ---------------------------------------------------------------------------
// K0 fused: blocks 0..255 compute h = X@W (fp16 out) + per-row projections
// (k2 folded in); blocks 256..8447 pack one adj row into bitmasks with MLP=8.
// GEMM smem reduced to 16KB (K split in 2) so pack blocks co-reside densely.
// ---------------------------------------------------------------------------
__global__ void __launch_bounds__(256) k0_fused(const float* __restrict__ x,
                                                const float* __restrict__ W,
                                                const int* __restrict__ adj,
                                                const float* __restrict__ a) {
    __shared__ float sx[32][128];        // 16KB (K half)
    __shared__ float red1[32][8];
    __shared__ float red2[32][8];
    const int tid = threadIdx.x;
    const int wid = tid >> 5, lane = tid & 31;

    if (blockIdx.x >= 256) {
        // ---- adj -> bitmask pack (one row per block), 8 loads in flight ----
        const int row = blockIdx.x - 256;
        const int4* arow4 = (const int4*)(adj + (size_t)row * NROW);
        int4 v[8];
#pragma unroll
        for (int u = 0; u < 8; ++u)
            v[u] = __ldg(&arow4[(wid + u * 8) * 32 + lane]);
#pragma unroll
        for (int u = 0; u < 8; ++u) {
            uint32_t b0 = __ballot_sync(0xffffffffu, v[u].x > 0);
            uint32_t b1 = __ballot_sync(0xffffffffu, v[u].y > 0);
            uint32_t b2 = __ballot_sync(0xffffffffu, v[u].z > 0);
            uint32_t b3 = __ballot_sync(0xffffffffu, v[u].w > 0);
            if (lane == 0)
                g_abits[(size_t)row * NGRP + wid + u * 8] =
                    make_uint4(b0, b1, b2, b3);
        }
        return;
    }

    // ---- h = X@W: 32 rows per block, thread = output column f ----
    const int row0 = blockIdx.x * 32;
    const int f = tid;
    const float a1 = __ldg(&a[f]);          // src weight
    const float a2 = __ldg(&a[FDIM + f]);   // dst weight

    float acc[32];
#pragma unroll
    for (int r = 0; r < 32; ++r) acc[r] = 0.f;

#pragma unroll
    for (int kh = 0; kh < 2; ++kh) {
        // load 32 x 128 X slab
#pragma unroll
        for (int it = 0; it < 4; ++it) {
            int idx = tid + it * 256;          // 0..1023 float4
            int r = idx >> 5, c4 = (idx & 31) << 2;
            *(float4*)(&sx[r][c4]) =
                *(const float4*)(&x[(size_t)(row0 + r) * FDIM + kh * 128 + c4]);
        }
        __syncthreads();

        for (int k = 0; k < 128; k += 4) {
            const int kg = kh * 128 + k;
            float w0 = __ldg(&W[(kg + 0) * FDIM + f]);
            float w1 = __ldg(&W[(kg + 1) * FDIM + f]);
            float w2 = __ldg(&W[(kg + 2) * FDIM + f]);
            float w3 = __ldg(&W[(kg + 3) * FDIM + f]);
#pragma unroll
            for (int r = 0; r < 32; ++r) {
                float4 v = *(const float4*)(&sx[r][k]);
                acc[r] = fmaf(v.x, w0, acc[r]);
                acc[r] = fmaf(v.y, w1, acc[r]);
                acc[r] = fmaf(v.z, w2, acc[r]);
                acc[r] = fmaf(v.w, w3, acc[r]);
            }
        }
        __syncthreads();
    }

    // fp16 copy of h
#pragma unroll
    for (int r = 0; r < 32; ++r)
        g_hh[(size_t)(row0 + r) * FDIM + f] = __float2half(acc[r]);

    // ---- fused k2: per-row src/dst projections via block reduction ----
#pragma unroll
    for (int r = 0; r < 32; ++r) {
        float v1 = acc[r] * a1;
        float v2 = acc[r] * a2;
#pragma unroll
        for (int off = 16; off; off >>= 1) {
            v1 += __shfl_xor_sync(0xffffffffu, v1, off);
            v2 += __shfl_xor_sync(0xffffffffu, v2, off);
        }
        if (lane == 0) { red1[r][wid] = v1; red2[r][wid] = v2; }
    }
    __syncthreads();
    if (tid < 32) {
        float s1 = 0.f, s2 = 0.f;
#pragma unroll
        for (int w = 0; w < 8; ++w) { s1 += red1[tid][w]; s2 += red2[tid][w]; }
        g_dE[row0 + tid] = make_float4(s2, expf(s2), expf(0.2f * s2), s1);
        g_F [row0 + tid] = expf(-0.8f * s1);
    }
}

// ---------------------------------------------------------------------------
// K4: fused unnormalized-softmax x GEMM (HMMA), 512 threads, 16 warps.
//     EXACT round-12 body (measured best k4 = ~175us).
// ---------------------------------------------------------------------------
struct K4S {
    __half sP[2][MT][72];     // U tiles (A operand), padded
    __half sH[2][KC][264];    // h tiles (B operand), padded
    float  sZ[MT];
    float  sZr[MT];
};

__global__ void __launch_bounds__(512) k4_main(float* __restrict__ out) {
    extern __shared__ char smraw[];
    K4S& sm = *reinterpret_cast<K4S*>(smraw);

    const int tid  = threadIdx.x;
    const int wid  = tid >> 5, lane = tid & 31;
    const int row0 = blockIdx.x * MT;
    const int wmi  = wid & 1;           // M half (32 rows)
    const int wn   = (wid >> 1) * 32;   // N group (32 cols)
    const int rb   = wid * 4;           // P-gen rows (4 per warp)

    float srcI[4], fI[4];
#pragma unroll
    for (int i = 0; i < 4; ++i) {
        srcI[i] = g_dE[row0 + rb + i].w;
        fI[i]   = g_F [row0 + rb + i];
    }

    // bitmask register cache (grp 0), dE registers (chunk 0)
    uint4 qc[4];
#pragma unroll
    for (int i = 0; i < 4; ++i)
        qc[i] = __ldg(&g_abits[(size_t)(row0 + rb + i) * NGRP]);
    float4 deA = __ldg(&g_dE[2 * lane]);
    float4 deB = __ldg(&g_dE[2 * lane + 1]);

    // prologue: prefetch h chunk 0 (2048 x 16B over 512 threads)
#pragma unroll
    for (int it = 0; it < 4; ++it) {
        const int idx = tid + it * 512;
        const int r = idx >> 5, c8 = (idx & 31) << 3;
        cp16(smem_u32(&sm.sH[0][r][c8]), &g_hh[(size_t)r * FDIM + c8]);
    }
    cp_commit();

    float acc[2][4][4];
#pragma unroll
    for (int mt = 0; mt < 2; ++mt)
#pragma unroll
        for (int nt = 0; nt < 4; ++nt)
#pragma unroll
            for (int q = 0; q < 4; ++q) acc[mt][nt][q] = 0.f;

    float Zp[4] = {0.f, 0.f, 0.f, 0.f};

    const int w0i = (2 * lane) & 3;
    const int w1i = (2 * lane + 1) & 3;
    const int b0l = (2 * lane) >> 2;
    const int b1l = (2 * lane + 1) >> 2;

    for (int s = 0; s < NCH; ++s) {
        const int buf = s & 1;

        // ---- P-gen chunk s: 4 rows, lane owns j-pair {2l, 2l+1} ----
        {
            const int sh = (s & 1) << 4;
            const int b0 = sh + b0l, b1 = sh + b1l;
#pragma unroll
            for (int i = 0; i < 4; ++i) {
                const uint32_t qa[4] = {qc[i].x, qc[i].y, qc[i].z, qc[i].w};
                float v0 = (srcI[i] + deA.x > 0.f) ? deA.y : fI[i] * deA.z;
                v0 = ((qa[w0i] >> b0) & 1u) ? v0 : 0.f;
                float v1 = (srcI[i] + deB.x > 0.f) ? deB.y : fI[i] * deB.z;
                v1 = ((qa[w1i] >> b1) & 1u) ? v1 : 0.f;
                Zp[i] += v0 + v1;
                *(__half2*)(&sm.sP[buf][rb + i][2 * lane]) =
                    __floats2half2_rn(v0, v1);
            }
        }

        // ---- register prefetch for chunk s+1 (covered by MMA below) ----
        float4 nA = deA, nB = deB;
        if (s + 1 < NCH) {
            const int j1 = (s + 1) * KC;
            nA = __ldg(&g_dE[j1 + 2 * lane]);
            nB = __ldg(&g_dE[j1 + 2 * lane + 1]);
            if (s & 1) {  // next chunk starts a new 128-j group
                const int ng = (s + 1) >> 1;
#pragma unroll
                for (int i = 0; i < 4; ++i)
                    qc[i] = __ldg(&g_abits[(size_t)(row0 + rb + i) * NGRP + ng]);
            }
        }

        cp_wait_all();       // h chunk s resident
        __syncthreads();     // sP/sH visible; prior chunk's reads complete

        // ---- prefetch h chunk s+1 ----
        if (s + 1 < NCH) {
            const int jn = (s + 1) * KC;
            const int nb = buf ^ 1;
#pragma unroll
            for (int it = 0; it < 4; ++it) {
                const int idx = tid + it * 512;
                const int r = idx >> 5, c8 = (idx & 31) << 3;
                cp16(smem_u32(&sm.sH[nb][r][c8]),
                     &g_hh[(size_t)(jn + r) * FDIM + c8]);
            }
            cp_commit();
        }

        // ---- MMA: warp covers 32(M) x 32(N), 4 k-steps ----
#pragma unroll
        for (int kk = 0; kk < KC; kk += 16) {
            uint32_t Af[2][4];
#pragma unroll
            for (int mt = 0; mt < 2; ++mt) {
                const uint32_t aa = smem_u32(
                    &sm.sP[buf][wmi * 32 + mt * 16 + (lane & 15)]
                          [kk + ((lane >> 4) << 3)]);
                asm volatile(
                    "ldmatrix.sync.aligned.m8n8.x4.shared.b16 {%0,%1,%2,%3}, [%4];\n"
                    : "=r"(Af[mt][0]), "=r"(Af[mt][1]),
                      "=r"(Af[mt][2]), "=r"(Af[mt][3]) : "r"(aa));
            }
#pragma unroll
            for (int bt = 0; bt < 2; ++bt) {
                uint32_t Bf[4];
                const uint32_t ba = smem_u32(
                    &sm.sH[buf][kk + (lane & 15)]
                          [wn + bt * 16 + ((lane >> 4) << 3)]);
                asm volatile(
                    "ldmatrix.sync.aligned.m8n8.x4.trans.shared.b16 {%0,%1,%2,%3}, [%4];\n"
                    : "=r"(Bf[0]), "=r"(Bf[1]), "=r"(Bf[2]), "=r"(Bf[3]) : "r"(ba));
#pragma unroll
                for (int mt = 0; mt < 2; ++mt) {
                    asm volatile(
                        "mma.sync.aligned.m16n8k16.row.col.f32.f16.f16.f32 "
                        "{%0,%1,%2,%3}, {%4,%5,%6,%7}, {%8,%9}, {%0,%1,%2,%3};\n"
                        : "+f"(acc[mt][2 * bt][0]), "+f"(acc[mt][2 * bt][1]),
                          "+f"(acc[mt][2 * bt][2]), "+f"(acc[mt][2 * bt][3])
                        : "r"(Af[mt][0]), "r"(Af[mt][1]), "r"(Af[mt][2]), "r"(Af[mt][3]),
                          "r"(Bf[0]), "r"(Bf[1]));
                    asm volatile(
                        "mma.sync.aligned.m16n8k16.row.col.f32.f16.f16.f32 "
                        "{%0,%1,%2,%3}, {%4,%5,%6,%7}, {%8,%9}, {%0,%1,%2,%3};\n"
                        : "+f"(acc[mt][2 * bt + 1][0]), "+f"(acc[mt][2 * bt + 1][1]),
                          "+f"(acc[mt][2 * bt + 1][2]), "+f"(acc[mt][2 * bt + 1][3])
                        : "r"(Af[mt][0]), "r"(Af[mt][1]), "r"(Af[mt][2]), "r"(Af[mt][3]),
                          "r"(Bf[2]), "r"(Bf[3]));
                }
            }
        }

        deA = nA; deB = nB;
    }

    // ---- Z reduction (16 warps x 4 rows = 64) ----
#pragma unroll
    for (int i = 0; i < 4; ++i) {
        float z = Zp[i];
#pragma unroll
        for (int off = 16; off; off >>= 1)
            z += __shfl_xor_sync(0xffffffffu, z, off);
        if (lane == 0) sm.sZ[rb + i] = z;
    }
    __syncthreads();
    if (tid < MT) sm.sZr[tid] = 1.0f / sm.sZ[tid];
    __syncthreads();

    // ---- epilogue: scale by 1/Z, ReLU, fp32 store ----
    const int g  = lane >> 2;
    const int tq = lane & 3;
#pragma unroll
    for (int mt = 0; mt < 2; ++mt) {
        const int lr0 = wmi * 32 + mt * 16 + g;
        const float iz0 = sm.sZr[lr0];
        const float iz1 = sm.sZr[lr0 + 8];
#pragma unroll
        for (int nt = 0; nt < 4; ++nt) {
            const int col = wn + nt * 8 + tq * 2;
            const int r0  = row0 + lr0;
            float2 v0 = make_float2(fmaxf(acc[mt][nt][0] * iz0, 0.f),
                                    fmaxf(acc[mt][nt][1] * iz0, 0.f));
            float2 v1 = make_float2(fmaxf(acc[mt][nt][2] * iz1, 0.f),
                                    fmaxf(acc[mt][nt][3] * iz1, 0.f));
            *(float2*)(&out[(size_t)r0 * FDIM + col])       = v0;
            *(float2*)(&out[(size_t)(r0 + 8) * FDIM + col]) = v1;
        }
    }
}

// ---------------------------------------------------------------------------
extern "C" void kernel_launch(void* const* d_in, const int* in_sizes, int n_in,
                              void* d_out, int out_size) {
    const float* input_ = (const float*)d_in[0];
    const int*   adj    = (const int*)d_in[1];
    const float* W      = (const float*)d_in[2];
    const float* a      = (const float*)d_in[3];
    float*       out    = (float*)d_out;

    static int attr_set = 0;
    const int k4_smem = (int)sizeof(K4S);
    if (!attr_set) {
        cudaFuncSetAttribute(k4_main,
                             cudaFuncAttributeMaxDynamicSharedMemorySize,
                             k4_smem);
        attr_set = 1;
    }

    k0_fused<<<256 + NROW, 256>>>(input_, W, adj, a);  // GEMM+proj ∥ adj pack
    k4_main<<<NROW / MT, 512, k4_smem>>>(out);
}

// round 16
// speedup vs baseline: 1.0684x; 1.0684x over previous
#include <cuda_runtime.h>
#include <cuda_fp16.h>
#include <cstdint>

#define NROW 8192
#define FDIM 256
#define MT   64
#define KC   64
#define NCH  (NROW / KC)
#define NGRP (NROW / 128)

// ---------------- device globals (no runtime allocation) -------------------
__device__ float  g_h [NROW * FDIM];     // h = X@W (fp32)
__device__ __half g_hh[NROW * FDIM];     // h fp16 row-major (B operand)
__device__ float4 g_dE[NROW];            // (dst, e^dst, e^{0.2 dst}, src)
__device__ float  g_F [NROW];            // e^{-0.8 src}
__device__ uint4  g_abits[NROW * NGRP];  // adj bits: grp g, word u, bit l = adj[r][g*128+4l+u]

static __device__ __forceinline__ uint32_t smem_u32(const void* p) {
    return (uint32_t)__cvta_generic_to_shared(p);
}
static __device__ __forceinline__ void cp16(uint32_t dst, const void* src) {
    asm volatile("cp.async.cg.shared.global [%0], [%1], 16;\n" :: "r"(dst), "l"(src));
}
static __device__ __forceinline__ void cp_commit() {
    asm volatile("cp.async.commit_group;\n" ::: "memory");
}
static __device__ __forceinline__ void cp_wait_all() {
    asm volatile("cp.async.wait_group 0;\n" ::: "memory");
}

// ---------------------------------------------------------------------------
// K0 fused: blocks 0..255 compute h = X@W (+fp16 copy) — byte-identical to the
// round-12 GEMM path; blocks 256..8447 pack one adj row into bitmasks, now
// with 8 loads in flight per lane (MLP=8) before the ballot chain.
// ---------------------------------------------------------------------------
__global__ void __launch_bounds__(256) k0_fused(const float* __restrict__ x,
                                                const float* __restrict__ W,
                                                const int* __restrict__ adj) {
    __shared__ float sx[32][256];
    const int tid = threadIdx.x;

    if (blockIdx.x >= 256) {
        // ---- adj -> bitmask pack (one row per block), MLP=8 ----
        const int row = blockIdx.x - 256;
        const int wid = tid >> 5, lane = tid & 31;
        const int4* arow4 = (const int4*)(adj + (size_t)row * NROW);
        int4 v[8];
#pragma unroll
        for (int u = 0; u < 8; ++u)
            v[u] = __ldg(&arow4[(wid + u * 8) * 32 + lane]);
#pragma unroll
        for (int u = 0; u < 8; ++u) {
            uint32_t b0 = __ballot_sync(0xffffffffu, v[u].x > 0);
            uint32_t b1 = __ballot_sync(0xffffffffu, v[u].y > 0);
            uint32_t b2 = __ballot_sync(0xffffffffu, v[u].z > 0);
            uint32_t b3 = __ballot_sync(0xffffffffu, v[u].w > 0);
            if (lane == 0)
                g_abits[(size_t)row * NGRP + wid + u * 8] =
                    make_uint4(b0, b1, b2, b3);
        }
        return;
    }

    // ---- h = X@W: 32 rows per block, thread = output column ----
    const int row0 = blockIdx.x * 32;
#pragma unroll
    for (int it = 0; it < 8; ++it) {
        int idx = tid + it * 256;
        int r = idx >> 6, c4 = (idx & 63) << 2;
        *(float4*)(&sx[r][c4]) = *(const float4*)(&x[(size_t)(row0 + r) * FDIM + c4]);
    }
    __syncthreads();

    float acc[32];
#pragma unroll
    for (int r = 0; r < 32; ++r) acc[r] = 0.f;

    const int f = tid;
    for (int k = 0; k < 256; k += 4) {
        float w0 = __ldg(&W[(k + 0) * FDIM + f]);
        float w1 = __ldg(&W[(k + 1) * FDIM + f]);
        float w2 = __ldg(&W[(k + 2) * FDIM + f]);
        float w3 = __ldg(&W[(k + 3) * FDIM + f]);
#pragma unroll
        for (int r = 0; r < 32; ++r) {
            float4 v = *(const float4*)(&sx[r][k]);
            acc[r] = fmaf(v.x, w0, acc[r]);
            acc[r] = fmaf(v.y, w1, acc[r]);
            acc[r] = fmaf(v.z, w2, acc[r]);
            acc[r] = fmaf(v.w, w3, acc[r]);
        }
    }
#pragma unroll
    for (int r = 0; r < 32; ++r) {
        g_h [(size_t)(row0 + r) * FDIM + f] = acc[r];
        g_hh[(size_t)(row0 + r) * FDIM + f] = __float2half(acc[r]);
    }
}

// ---------------------------------------------------------------------------
// K2: per-row src/dst projections + exp tables + row factor (round-12 exact)
// ---------------------------------------------------------------------------
__global__ void __launch_bounds__(256) k2_vec(const float* __restrict__ a) {
    const int tid = threadIdx.x;
    const int wid = tid >> 5, lane = tid & 31;
    const int row = blockIdx.x * 8 + wid;
    const float* hr = g_h + (size_t)row * FDIM;

    float s1 = 0.f, s2 = 0.f;
#pragma unroll
    for (int i = 0; i < 8; ++i) {
        int c = lane + i * 32;
        float v = hr[c];
        s1 += v * __ldg(&a[c]);          // src
        s2 += v * __ldg(&a[FDIM + c]);   // dst
    }
#pragma unroll
    for (int off = 16; off; off >>= 1) {
        s1 += __shfl_xor_sync(0xffffffffu, s1, off);
        s2 += __shfl_xor_sync(0xffffffffu, s2, off);
    }
    if (lane == 0) {
        g_dE[row] = make_float4(s2, expf(s2), expf(0.2f * s2), s1);
        g_F [row] = expf(-0.8f * s1);
    }
}

// ---------------------------------------------------------------------------
// K4: fused unnormalized-softmax x GEMM (HMMA), 512 threads, 16 warps.
//     EXACT round-12 body (measured best k4 = ~175us).
// ---------------------------------------------------------------------------
struct K4S {
    __half sP[2][MT][72];     // U tiles (A operand), padded
    __half sH[2][KC][264];    // h tiles (B operand), padded
    float  sZ[MT];
    float  sZr[MT];
};

__global__ void __launch_bounds__(512) k4_main(float* __restrict__ out) {
    extern __shared__ char smraw[];
    K4S& sm = *reinterpret_cast<K4S*>(smraw);

    const int tid  = threadIdx.x;
    const int wid  = tid >> 5, lane = tid & 31;
    const int row0 = blockIdx.x * MT;
    const int wmi  = wid & 1;           // M half (32 rows)
    const int wn   = (wid >> 1) * 32;   // N group (32 cols)
    const int rb   = wid * 4;           // P-gen rows (4 per warp)

    float srcI[4], fI[4];
#pragma unroll
    for (int i = 0; i < 4; ++i) {
        srcI[i] = g_dE[row0 + rb + i].w;
        fI[i]   = g_F [row0 + rb + i];
    }

    // bitmask register cache (grp 0), dE registers (chunk 0)
    uint4 qc[4];
#pragma unroll
    for (int i = 0; i < 4; ++i)
        qc[i] = __ldg(&g_abits[(size_t)(row0 + rb + i) * NGRP]);
    float4 deA = __ldg(&g_dE[2 * lane]);
    float4 deB = __ldg(&g_dE[2 * lane + 1]);

    // prologue: prefetch h chunk 0 (2048 x 16B over 512 threads)
#pragma unroll
    for (int it = 0; it < 4; ++it) {
        const int idx = tid + it * 512;
        const int r = idx >> 5, c8 = (idx & 31) << 3;
        cp16(smem_u32(&sm.sH[0][r][c8]), &g_hh[(size_t)r * FDIM + c8]);
    }
    cp_commit();

    float acc[2][4][4];
#pragma unroll
    for (int mt = 0; mt < 2; ++mt)
#pragma unroll
        for (int nt = 0; nt < 4; ++nt)
#pragma unroll
            for (int q = 0; q < 4; ++q) acc[mt][nt][q] = 0.f;

    float Zp[4] = {0.f, 0.f, 0.f, 0.f};

    const int w0i = (2 * lane) & 3;
    const int w1i = (2 * lane + 1) & 3;
    const int b0l = (2 * lane) >> 2;
    const int b1l = (2 * lane + 1) >> 2;

    for (int s = 0; s < NCH; ++s) {
        const int buf = s & 1;

        // ---- P-gen chunk s: 4 rows, lane owns j-pair {2l, 2l+1} ----
        {
            const int sh = (s & 1) << 4;
            const int b0 = sh + b0l, b1 = sh + b1l;
#pragma unroll
            for (int i = 0; i < 4; ++i) {
                const uint32_t qa[4] = {qc[i].x, qc[i].y, qc[i].z, qc[i].w};
                float v0 = (srcI[i] + deA.x > 0.f) ? deA.y : fI[i] * deA.z;
                v0 = ((qa[w0i] >> b0) & 1u) ? v0 : 0.f;
                float v1 = (srcI[i] + deB.x > 0.f) ? deB.y : fI[i] * deB.z;
                v1 = ((qa[w1i] >> b1) & 1u) ? v1 : 0.f;
                Zp[i] += v0 + v1;
                *(__half2*)(&sm.sP[buf][rb + i][2 * lane]) =
                    __floats2half2_rn(v0, v1);
            }
        }

        // ---- register prefetch for chunk s+1 (covered by MMA below) ----
        float4 nA = deA, nB = deB;
        if (s + 1 < NCH) {
            const int j1 = (s + 1) * KC;
            nA = __ldg(&g_dE[j1 + 2 * lane]);
            nB = __ldg(&g_dE[j1 + 2 * lane + 1]);
            if (s & 1) {  // next chunk starts a new 128-j group
                const int ng = (s + 1) >> 1;
#pragma unroll
                for (int i = 0; i < 4; ++i)
                    qc[i] = __ldg(&g_abits[(size_t)(row0 + rb + i) * NGRP + ng]);
            }
        }

        cp_wait_all();       // h chunk s resident
        __syncthreads();     // sP/sH visible; prior chunk's reads complete

        // ---- prefetch h chunk s+1 ----
        if (s + 1 < NCH) {
            const int jn = (s + 1) * KC;
            const int nb = buf ^ 1;
#pragma unroll
            for (int it = 0; it < 4; ++it) {
                const int idx = tid + it * 512;
                const int r = idx >> 5, c8 = (idx & 31) << 3;
                cp16(smem_u32(&sm.sH[nb][r][c8]),
                     &g_hh[(size_t)(jn + r) * FDIM + c8]);
            }
            cp_commit();
        }

        // ---- MMA: warp covers 32(M) x 32(N), 4 k-steps ----
#pragma unroll
        for (int kk = 0; kk < KC; kk += 16) {
            uint32_t Af[2][4];
#pragma unroll
            for (int mt = 0; mt < 2; ++mt) {
                const uint32_t aa = smem_u32(
                    &sm.sP[buf][wmi * 32 + mt * 16 + (lane & 15)]
                          [kk + ((lane >> 4) << 3)]);
                asm volatile(
                    "ldmatrix.sync.aligned.m8n8.x4.shared.b16 {%0,%1,%2,%3}, [%4];\n"
                    : "=r"(Af[mt][0]), "=r"(Af[mt][1]),
                      "=r"(Af[mt][2]), "=r"(Af[mt][3]) : "r"(aa));
            }
#pragma unroll
            for (int bt = 0; bt < 2; ++bt) {
                uint32_t Bf[4];
                const uint32_t ba = smem_u32(
                    &sm.sH[buf][kk + (lane & 15)]
                          [wn + bt * 16 + ((lane >> 4) << 3)]);
                asm volatile(
                    "ldmatrix.sync.aligned.m8n8.x4.trans.shared.b16 {%0,%1,%2,%3}, [%4];\n"
                    : "=r"(Bf[0]), "=r"(Bf[1]), "=r"(Bf[2]), "=r"(Bf[3]) : "r"(ba));
#pragma unroll
                for (int mt = 0; mt < 2; ++mt) {
                    asm volatile(
                        "mma.sync.aligned.m16n8k16.row.col.f32.f16.f16.f32 "
                        "{%0,%1,%2,%3}, {%4,%5,%6,%7}, {%8,%9}, {%0,%1,%2,%3};\n"
                        : "+f"(acc[mt][2 * bt][0]), "+f"(acc[mt][2 * bt][1]),
                          "+f"(acc[mt][2 * bt][2]), "+f"(acc[mt][2 * bt][3])
                        : "r"(Af[mt][0]), "r"(Af[mt][1]), "r"(Af[mt][2]), "r"(Af[mt][3]),
                          "r"(Bf[0]), "r"(Bf[1]));
                    asm volatile(
                        "mma.sync.aligned.m16n8k16.row.col.f32.f16.f16.f32 "
                        "{%0,%1,%2,%3}, {%4,%5,%6,%7}, {%8,%9}, {%0,%1,%2,%3};\n"
                        : "+f"(acc[mt][2 * bt + 1][0]), "+f"(acc[mt][2 * bt + 1][1]),
                          "+f"(acc[mt][2 * bt + 1][2]), "+f"(acc[mt][2 * bt + 1][3])
                        : "r"(Af[mt][0]), "r"(Af[mt][1]), "r"(Af[mt][2]), "r"(Af[mt][3]),
                          "r"(Bf[2]), "r"(Bf[3]));
                }
            }
        }

        deA = nA; deB = nB;
    }

    // ---- Z reduction (16 warps x 4 rows = 64) ----
#pragma unroll
    for (int i = 0; i < 4; ++i) {
        float z = Zp[i];
#pragma unroll
        for (int off = 16; off; off >>= 1)
            z += __shfl_xor_sync(0xffffffffu, z, off);
        if (lane == 0) sm.sZ[rb + i] = z;
    }
    __syncthreads();
    if (tid < MT) sm.sZr[tid] = 1.0f / sm.sZ[tid];
    __syncthreads();

    // ---- epilogue: scale by 1/Z, ReLU, fp32 store ----
    const int g  = lane >> 2;
    const int tq = lane & 3;
#pragma unroll
    for (int mt = 0; mt < 2; ++mt) {
        const int lr0 = wmi * 32 + mt * 16 + g;
        const float iz0 = sm.sZr[lr0];
        const float iz1 = sm.sZr[lr0 + 8];
#pragma unroll
        for (int nt = 0; nt < 4; ++nt) {
            const int col = wn + nt * 8 + tq * 2;
            const int r0  = row0 + lr0;
            float2 v0 = make_float2(fmaxf(acc[mt][nt][0] * iz0, 0.f),
                                    fmaxf(acc[mt][nt][1] * iz0, 0.f));
            float2 v1 = make_float2(fmaxf(acc[mt][nt][2] * iz1, 0.f),
                                    fmaxf(acc[mt][nt][3] * iz1, 0.f));
            *(float2*)(&out[(size_t)r0 * FDIM + col])       = v0;
            *(float2*)(&out[(size_t)(r0 + 8) * FDIM + col]) = v1;
        }
    }
}

// ---------------------------------------------------------------------------
extern "C" void kernel_launch(void* const* d_in, const int* in_sizes, int n_in,
                              void* d_out, int out_size) {
    const float* input_ = (const float*)d_in[0];
    const int*   adj    = (const int*)d_in[1];
    const float* W      = (const float*)d_in[2];
    const float* a      = (const float*)d_in[3];
    float*       out    = (float*)d_out;

    static int attr_set = 0;
    const int k4_smem = (int)sizeof(K4S);
    if (!attr_set) {
        cudaFuncSetAttribute(k4_main,
                             cudaFuncAttributeMaxDynamicSharedMemorySize,
                             k4_smem);
        attr_set = 1;
    }

    k0_fused<<<256 + NROW, 256>>>(input_, W, adj);   // k1 GEMM ∥ adj pack
    k2_vec<<<NROW / 8, 256>>>(a);
    k4_main<<<NROW / MT, 512, k4_smem>>>(out);
}